// round 14
// baseline (speedup 1.0000x reference)
#include <cuda_runtime.h>
#include <cuda_bf16.h>
#include <cstdint>
#include <cstddef>

// ---------------------------------------------------------------------------
// DynamicDecoder: H=256, P=16, T=4, B=32, M=600
//   preU[head][n][4096] = U[n,:512] @ W1[:, :512]^T   -- mma.sync bf16 3-term
//   per step/head: rw = r@W1_r^T + b1 (tiny); m1 = max_p(preU + rw)
//                  m2max = 16-group max of (m1 @ W2^T + b2)  -- mma.sync bf16
//                  alpha = max_j16(cat[m1,m2max].W12^T + b12) + mask
//                  log-softmax reduce -> argmax / nll
// fp32 operands split into bf16 hi/lo; 3-term MMA (hh,hl,lh) in fp32 accum.
// GEMM: 3-stage cp.async pipeline. Launch order puts gemm_mma<0> at index 5
// so the fixed ncu window (-s 5 -c 1) profiles it.
// ---------------------------------------------------------------------------

#define Bz 32
#define Mz 600
#define Hz 256
#define NR (Bz*Mz)      // 19200
#define HPz 4096
#define KPRE 512
#define KM2 256

typedef unsigned long long u64;
typedef __nv_bfloat16 bf16;

// ------------------------- device scratch (no allocs) ----------------------
__device__ __align__(16) float g_pre[2ull*NR*HPz];        // 629 MB
__device__ __align__(16) float g_m1[(size_t)NR*Hz];
__device__ __align__(16) bf16  g_m1h[(size_t)NR*Hz];
__device__ __align__(16) bf16  g_m1l[(size_t)NR*Hz];
__device__ __align__(16) float g_m2max[(size_t)NR*Hz];
__device__ __align__(16) float g_alpha[NR];
__device__ __align__(16) float g_rw[Bz*HPz];
__device__ __align__(16) float g_ucat[Bz*1024];
__device__ __align__(16) float g_gates[Bz*1024];
__device__ __align__(16) float g_h[Bz*Hz];
__device__ __align__(16) float g_c[Bz*Hz];
__device__ __align__(16) float g_r[Bz*Hz];
__device__ __align__(16) bf16  g_Uh[(size_t)NR*KPRE], g_Ul[(size_t)NR*KPRE];
__device__ __align__(16) bf16  g_W1sh[(size_t)HPz*KPRE], g_W1sl[(size_t)HPz*KPRE];
__device__ __align__(16) bf16  g_W1eh[(size_t)HPz*KPRE], g_W1el[(size_t)HPz*KPRE];
__device__ __align__(16) bf16  g_W2sh[(size_t)HPz*KM2],  g_W2sl[(size_t)HPz*KM2];
__device__ __align__(16) bf16  g_W2eh[(size_t)HPz*KM2],  g_W2el[(size_t)HPz*KM2];
__device__ float g_nll[Bz];
__device__ int   g_amax_i[Bz];
__device__ int   g_si[Bz], g_ei[Bz], g_ms[Bz], g_me[Bz];
__device__ int   g_res_s[4][Bz], g_res_e[4][Bz];
__device__ int   g_res_ms[4][Bz], g_res_me[4][Bz];
__device__ float g_loss;

// ------------------------- helpers -----------------------------------------
__device__ __forceinline__ float sigm(float x) { return 1.f / (1.f + expf(-x)); }

__device__ __forceinline__ uint32_t s2u(const void* p) {
    uint32_t a;
    asm("{ .reg .u64 t; cvta.to.shared.u64 t, %1; cvt.u32.u64 %0, t; }"
        : "=r"(a) : "l"(p));
    return a;
}
#define SWZ(x) ((x) ^ (((x) >> 3) & 0x70))

__device__ __forceinline__ void cpasync16(uint32_t dst, const void* src) {
    asm volatile("cp.async.cg.shared.global [%0], [%1], 16;" :: "r"(dst), "l"(src));
}
#define CP_COMMIT() asm volatile("cp.async.commit_group;" ::: "memory")
#define CP_WAIT(n)  asm volatile("cp.async.wait_group %0;" :: "n"(n) : "memory")

__device__ __forceinline__ void ldmx4(uint32_t* r, uint32_t addr) {
    asm volatile("ldmatrix.sync.aligned.m8n8.x4.shared.b16 {%0,%1,%2,%3}, [%4];"
        : "=r"(r[0]), "=r"(r[1]), "=r"(r[2]), "=r"(r[3]) : "r"(addr));
}
__device__ __forceinline__ void mma_bf16(float* c, const uint32_t* a, const uint32_t* b) {
    asm volatile(
        "mma.sync.aligned.m16n8k16.row.col.f32.bf16.bf16.f32 "
        "{%0,%1,%2,%3}, {%4,%5,%6,%7}, {%8,%9}, {%0,%1,%2,%3};"
        : "+f"(c[0]), "+f"(c[1]), "+f"(c[2]), "+f"(c[3])
        : "r"(a[0]), "r"(a[1]), "r"(a[2]), "r"(a[3]), "r"(b[0]), "r"(b[1]));
}

// ------------------------- init ---------------------------------------------
__global__ void init_kernel(const int* __restrict__ dmask)
{
    __shared__ int ss[256];
    int b = blockIdx.x, tid = threadIdx.x;
    int s = 0;
    for (int m = tid; m < Mz; m += 256) s += dmask[b*Mz + m];
    ss[tid] = s; __syncthreads();
    for (int st = 128; st; st >>= 1) { if (tid < st) ss[tid] += ss[tid+st]; __syncthreads(); }
    if (tid == 0) { g_ei[b] = ss[0] - 1; g_si[b] = 0; if (b == 0) g_loss = 0.f; }
    g_h[b*Hz + tid] = 0.f;
    g_c[b*Hz + tid] = 0.f;
}

// ------------------------- fused fp32 -> bf16 hi/lo split (5 segments) ------
struct CvtSeg {
    const float* src; bf16* hi; bf16* lo;
    long long total; int srcStride; int C;
};
__global__ void cvt_fused_kernel(CvtSeg s0, CvtSeg s1, CvtSeg s2, CvtSeg s3, CvtSeg s4)
{
    long long i = (long long)blockIdx.x * blockDim.x + threadIdx.x;
    CvtSeg s;
    if (i < s0.total) s = s0;
    else { i -= s0.total;
        if (i < s1.total) s = s1;
        else { i -= s1.total;
            if (i < s2.total) s = s2;
            else { i -= s2.total;
                if (i < s3.total) s = s3;
                else { i -= s3.total;
                    if (i < s4.total) s = s4;
                    else return; } } } }
    long long r = i / s.C;
    int c = (int)(i - r * (long long)s.C);
    float x = s.src[r * (long long)s.srcStride + c];
    bf16 h = __float2bfloat16(x);
    s.hi[i] = h;
    s.lo[i] = __float2bfloat16(x - __bfloat162float(h));
}

// ------------------------- LSTM: gather / gates / activation ----------------
__global__ void gather_kernel(const float* __restrict__ U)
{
    int b = blockIdx.x, tid = threadIdx.x;
    int si = g_si[b], ei = g_ei[b];
    const float* us = U + ((size_t)b*Mz + si)*512;
    const float* ue = U + ((size_t)b*Mz + ei)*512;
    for (int k = tid; k < 512; k += 256) {
        g_ucat[b*1024 + k]       = us[k];
        g_ucat[b*1024 + 512 + k] = ue[k];
    }
}

__global__ void gates_kernel(const float* __restrict__ Wih,
                             const float* __restrict__ Whh,
                             const float* __restrict__ bih,
                             const float* __restrict__ bhh)
{
    __shared__ __align__(16) float sx[1280];
    int b = blockIdx.y, tid = threadIdx.x;
    int row = blockIdx.x*128 + tid;
    for (int k = tid; k < 1024; k += 128) sx[k]       = g_ucat[b*1024 + k];
    for (int k = tid; k < 256;  k += 128) sx[1024+k]  = g_h[b*Hz + k];
    __syncthreads();
    const float4* x4 = (const float4*)sx;
    const float4* w1 = (const float4*)(Wih + (size_t)row*1024);
    float a0=0.f, a1=0.f, a2=0.f, a3=0.f;
    #pragma unroll 8
    for (int k = 0; k < 256; k += 4) {
        float4 w, v;
        w = w1[k];   v = x4[k];   a0 += w.x*v.x + w.y*v.y + w.z*v.z + w.w*v.w;
        w = w1[k+1]; v = x4[k+1]; a1 += w.x*v.x + w.y*v.y + w.z*v.z + w.w*v.w;
        w = w1[k+2]; v = x4[k+2]; a2 += w.x*v.x + w.y*v.y + w.z*v.z + w.w*v.w;
        w = w1[k+3]; v = x4[k+3]; a3 += w.x*v.x + w.y*v.y + w.z*v.z + w.w*v.w;
    }
    const float4* w2 = (const float4*)(Whh + (size_t)row*256);
    const float4* h4 = x4 + 256;
    #pragma unroll 8
    for (int k = 0; k < 64; k += 4) {
        float4 w, v;
        w = w2[k];   v = h4[k];   a0 += w.x*v.x + w.y*v.y + w.z*v.z + w.w*v.w;
        w = w2[k+1]; v = h4[k+1]; a1 += w.x*v.x + w.y*v.y + w.z*v.z + w.w*v.w;
        w = w2[k+2]; v = h4[k+2]; a2 += w.x*v.x + w.y*v.y + w.z*v.z + w.w*v.w;
        w = w2[k+3]; v = h4[k+3]; a3 += w.x*v.x + w.y*v.y + w.z*v.z + w.w*v.w;
    }
    g_gates[b*1024 + row] = (a0+a1) + (a2+a3) + bih[row] + bhh[row];
}

__global__ void act_kernel()
{
    int b = blockIdx.x, i = threadIdx.x;
    float gi = g_gates[b*1024 + i], gf = g_gates[b*1024 + 256 + i];
    float gg = g_gates[b*1024 + 512 + i], go = g_gates[b*1024 + 768 + i];
    float c = sigm(gf)*g_c[b*Hz+i] + sigm(gi)*tanhf(gg);
    g_c[b*Hz+i] = c;
    g_h[b*Hz+i] = sigm(go)*tanhf(c);
}

// ------------------------- r = tanh(cat[h,ucat] @ Wlin^T) -------------------
__global__ void r_kernel(const float* __restrict__ Wlin)
{
    __shared__ __align__(16) float sx[1280];
    int b = blockIdx.y, tid = threadIdx.x;
    int row = blockIdx.x*128 + tid;
    for (int k = tid; k < 256;  k += 128) sx[k]     = g_h[b*Hz + k];
    for (int k = tid; k < 1024; k += 128) sx[256+k] = g_ucat[b*1024 + k];
    __syncthreads();
    const float4* x4 = (const float4*)sx;
    const float4* w  = (const float4*)(Wlin + (size_t)row*1280);
    float a0=0.f, a1=0.f, a2=0.f, a3=0.f;
    #pragma unroll 8
    for (int k = 0; k < 320; k += 4) {
        float4 wv, v;
        wv = w[k];   v = x4[k];   a0 += wv.x*v.x + wv.y*v.y + wv.z*v.z + wv.w*v.w;
        wv = w[k+1]; v = x4[k+1]; a1 += wv.x*v.x + wv.y*v.y + wv.z*v.z + wv.w*v.w;
        wv = w[k+2]; v = x4[k+2]; a2 += wv.x*v.x + wv.y*v.y + wv.z*v.z + wv.w*v.w;
        wv = w[k+3]; v = x4[k+3]; a3 += wv.x*v.x + wv.y*v.y + wv.z*v.z + wv.w*v.w;
    }
    g_r[b*Hz + row] = tanhf((a0+a1) + (a2+a3));
}

// ------------------------- rw = r @ W1_r^T + b1 -----------------------------
__global__ void rw_kernel(const float* __restrict__ W1, const float* __restrict__ b1)
{
    __shared__ __align__(16) float sr[256];
    int b = blockIdx.y, tid = threadIdx.x;
    int j = blockIdx.x*256 + tid;
    sr[tid] = g_r[b*Hz + tid];
    __syncthreads();
    const float4* w  = (const float4*)(W1 + (size_t)j*768 + 512);
    const float4* r4 = (const float4*)sr;
    float acc = b1[j];
    #pragma unroll 8
    for (int k = 0; k < 64; k++) {
        float4 wv = w[k], rv = r4[k];
        acc += wv.x*rv.x + wv.y*rv.y + wv.z*rv.z + wv.w*rv.w;
    }
    g_rw[b*HPz + j] = acc;
}

// ------------------------- m1 = max_p(preU + rw); also split to bf16 --------
__global__ void m1max_kernel(int head)
{
    int n = blockIdx.x, h = threadIdx.x;
    int b = n / Mz;
    const float4* p = (const float4*)(g_pre + (size_t)head*((size_t)NR*HPz) + (size_t)n*HPz + h*16);
    const float4* r = (const float4*)(g_rw + b*HPz + h*16);
    float m = -1e38f;
    #pragma unroll
    for (int q = 0; q < 4; q++) {
        float4 a = p[q], c = r[q];
        m = fmaxf(m, fmaxf(fmaxf(a.x+c.x, a.y+c.y), fmaxf(a.z+c.z, a.w+c.w)));
    }
    g_m1[(size_t)n*Hz + h] = m;
    bf16 hh = __float2bfloat16(m);
    g_m1h[(size_t)n*Hz + h] = hh;
    g_m1l[(size_t)n*Hz + h] = __float2bfloat16(m - __bfloat162float(hh));
}

// ------------------------- mma.sync bf16 3-term GEMM (3-stage pipeline) -----
// C[128x128] per CTA. A rows Mbase.. (lda=K), B rows j0.. (ldb=K), NT form.
// 8 warps as 4(m) x 2(n); warp tile 32x64 via m16n8k16.
// EPI=0: store fp32 C to out (ldc=4096). EPI=1: +bias, 16-group max (ldc=256).
// smem: [0,512) bias; [1024, 1024+3*65536) three stages of {Ah,Al,Bh,Bl}.
#define GSMEM_TOTAL (1024 + 3*65536)

template<int EPI>
__global__ __launch_bounds__(256)
void gemm_mma(const bf16* __restrict__ Ah, const bf16* __restrict__ Al,
              const bf16* __restrict__ Bh, const bf16* __restrict__ Bl,
              const float* __restrict__ bias,
              float* __restrict__ out, int K)
{
    extern __shared__ __align__(1024) char smem[];
    uint32_t sb = s2u(smem);
    const int tid = threadIdx.x, wid = tid >> 5, lane = tid & 31;
    const int Mbase = blockIdx.y * 128, j0 = blockIdx.x * 128;

    if (EPI == 1 && tid < 128) ((float*)smem)[tid] = bias[j0 + tid];

    float acc[2][8][4];
    #pragma unroll
    for (int a = 0; a < 2; a++)
        #pragma unroll
        for (int b = 0; b < 8; b++)
            #pragma unroll
            for (int d = 0; d < 4; d++) acc[a][b][d] = 0.f;

    const int wm = (wid & 3) * 32, wn = (wid >> 2) * 64;
    // ldmatrix per-lane source coordinates
    const int arow = wm + (lane & 15);
    const int acol = (lane >> 4) << 4;                 // 0 or 16 bytes (k half)
    const int brow = wn + (lane & 7) + ((lane >> 4) << 3);
    const int bcol = ((lane >> 3) & 1) << 4;

    const int KB = K >> 6;

    auto load_stage = [&](int kb, int buf) {
        const int kofs = kb * 64;
        #pragma unroll
        for (int q = 0; q < 4; q++) {
            int i = q * 256 + tid;
            int r = i >> 3, c = i & 7;
            uint32_t dst = sb + 1024 + buf * 65536 + SWZ((uint32_t)(r * 128 + c * 16));
            size_t ga = (size_t)(Mbase + r) * K + kofs + c * 8;
            size_t gb = (size_t)(j0   + r) * K + kofs + c * 8;
            cpasync16(dst,         Ah + ga);
            cpasync16(dst + 16384, Al + ga);
            cpasync16(dst + 32768, Bh + gb);
            cpasync16(dst + 49152, Bl + gb);
        }
    };

    load_stage(0, 0); CP_COMMIT();
    if (KB > 1) { load_stage(1, 1); CP_COMMIT(); }

    for (int kb = 0; kb < KB; kb++) {
        if (kb + 1 < KB) { CP_WAIT(1); } else { CP_WAIT(0); }
        __syncthreads();
        int buf = kb % 3;
        uint32_t ab = sb + 1024 + buf * 65536;
        #pragma unroll
        for (int ks = 0; ks < 4; ks++) {
            uint32_t a_h[2][4], a_l[2][4], b_h[4][4], b_l[4][4];
            #pragma unroll
            for (int mt = 0; mt < 2; mt++) {
                uint32_t sw = SWZ((uint32_t)((arow + mt*16) * 128 + ks*32 + acol));
                ldmx4(a_h[mt], ab + sw);
                ldmx4(a_l[mt], ab + 16384 + sw);
            }
            #pragma unroll
            for (int np = 0; np < 4; np++) {
                uint32_t sw = SWZ((uint32_t)((brow + np*16) * 128 + ks*32 + bcol));
                ldmx4(b_h[np], ab + 32768 + sw);
                ldmx4(b_l[np], ab + 49152 + sw);
            }
            #pragma unroll
            for (int mt = 0; mt < 2; mt++)
                #pragma unroll
                for (int nt = 0; nt < 8; nt++) {
                    const uint32_t* bh2 = &b_h[nt >> 1][(nt & 1) * 2];
                    const uint32_t* bl2 = &b_l[nt >> 1][(nt & 1) * 2];
                    mma_bf16(acc[mt][nt], a_h[mt], bh2);
                    mma_bf16(acc[mt][nt], a_h[mt], bl2);
                    mma_bf16(acc[mt][nt], a_l[mt], bh2);
                }
        }
        __syncthreads();
        if (kb + 2 < KB) { load_stage(kb + 2, (kb + 2) % 3); CP_COMMIT(); }
    }

    if (EPI == 0) {
        #pragma unroll
        for (int mt = 0; mt < 2; mt++)
            #pragma unroll
            for (int nt = 0; nt < 8; nt++) {
                int row = Mbase + wm + mt*16 + (lane >> 2);
                int col = j0 + wn + nt*8 + 2*(lane & 3);
                *(float2*)(out + (size_t)row       * HPz + col) =
                    make_float2(acc[mt][nt][0], acc[mt][nt][1]);
                *(float2*)(out + (size_t)(row + 8) * HPz + col) =
                    make_float2(acc[mt][nt][2], acc[mt][nt][3]);
            }
    } else {
        float* Cs = (float*)(smem + 1024);   // reuse stage 0: 128x128 f32 = 64KB
        #pragma unroll
        for (int mt = 0; mt < 2; mt++)
            #pragma unroll
            for (int nt = 0; nt < 8; nt++) {
                int r0 = wm + mt*16 + (lane >> 2);
                int c0 = wn + nt*8 + 2*(lane & 3);
                Cs[r0*128 + c0]       = acc[mt][nt][0];
                Cs[r0*128 + c0 + 1]   = acc[mt][nt][1];
                Cs[(r0+8)*128 + c0]   = acc[mt][nt][2];
                Cs[(r0+8)*128 + c0+1] = acc[mt][nt][3];
            }
        __syncthreads();
        const float* sbias = (const float*)smem;
        for (int i = tid; i < 1024; i += 256) {
            int r = i >> 3, g = i & 7;
            const float* row = Cs + r*128 + g*16;
            const float* bb  = sbias + g*16;
            float m = -1e38f;
            #pragma unroll
            for (int k = 0; k < 16; k++) m = fmaxf(m, row[k] + bb[k]);
            out[(size_t)(Mbase + r) * Hz + blockIdx.x*8 + g] = m;
        }
    }
}

// ------------------------- alpha = max_j16(cat[m1,m2max].W12[j]+b12)+mask ---
__global__ void alpha_kernel(const float* __restrict__ W12,
                             const float* __restrict__ b12,
                             const int*   __restrict__ dmask)
{
    __shared__ __align__(16) float sw[16 * 512];
    __shared__ float sb[16];
    int tid = threadIdx.x;
    for (int i = tid; i < 8192; i += 256) sw[i] = W12[i];
    if (tid < 16) sb[tid] = b12[tid];
    __syncthreads();
    int w = tid >> 5, lane = tid & 31;
    int n = blockIdx.x * 8 + w;
    const float4* m1p = (const float4*)(g_m1    + (size_t)n*Hz);
    const float4* m2p = (const float4*)(g_m2max + (size_t)n*Hz);
    float4 a0 = m1p[lane], a1 = m1p[32 + lane];
    float4 c0 = m2p[lane], c1 = m2p[32 + lane];
    float vmax = -1e38f;
    #pragma unroll
    for (int j = 0; j < 16; j++) {
        const float4* wr = (const float4*)(sw + j*512);
        float4 w0 = wr[lane],      w1 = wr[32 + lane];
        float4 w2 = wr[64 + lane], w3 = wr[96 + lane];
        float p = a0.x*w0.x + a0.y*w0.y + a0.z*w0.z + a0.w*w0.w
                + a1.x*w1.x + a1.y*w1.y + a1.z*w1.z + a1.w*w1.w
                + c0.x*w2.x + c0.y*w2.y + c0.z*w2.z + c0.w*w2.w
                + c1.x*w3.x + c1.y*w3.y + c1.z*w3.z + c1.w*w3.w;
        #pragma unroll
        for (int s = 16; s; s >>= 1) p += __shfl_down_sync(0xffffffffu, p, s);
        if (lane == 0) vmax = fmaxf(vmax, p + sb[j]);
    }
    if (lane == 0) {
        int b = n / Mz, m = n - b*Mz;
        float mm = dmask[b*Mz + m] ? 0.f : -1e30f;
        g_alpha[n] = vmax + mm;
    }
}

// ------------------------- per-batch argmax + log-softmax reduce ------------
__global__ void reduce_kernel(const int* __restrict__ span, int col)
{
    __shared__ float sv[256];
    __shared__ int   sidx[256];
    int b = blockIdx.x, tid = threadIdx.x;
    const float* a = g_alpha + b*Mz;
    float lv = -1e38f; int li = 0;
    for (int m = tid; m < Mz; m += 256) { float v = a[m]; if (v > lv) { lv = v; li = m; } }
    sv[tid] = lv; sidx[tid] = li; __syncthreads();
    for (int s = 128; s; s >>= 1) {
        if (tid < s) {
            float v = sv[tid+s]; int i2 = sidx[tid+s];
            if (v > sv[tid] || (v == sv[tid] && i2 < sidx[tid])) { sv[tid] = v; sidx[tid] = i2; }
        }
        __syncthreads();
    }
    float amax = sv[0]; int ai = sidx[0];
    __syncthreads();
    float se = 0.f;
    for (int m = tid; m < Mz; m += 256) se += expf(a[m] - amax);
    sv[tid] = se; __syncthreads();
    for (int s = 128; s; s >>= 1) { if (tid < s) sv[tid] += sv[tid+s]; __syncthreads(); }
    if (tid == 0) {
        float logZ = amax + logf(sv[0]);
        int tgt = span[b*2 + col];
        g_nll[b]    = -(a[tgt] - logZ);
        g_amax_i[b] = ai;
    }
}

// ------------------------- control: s-phase (also regathers u_s) ------------
__global__ void ctrl_s_kernel(const float* __restrict__ U, int t)
{
    __shared__ int sidx[32];
    int tid = threadIdx.x;
    if (tid < 32) {
        int b = tid;
        float nll = g_nll[b];
        int idx = g_amax_i[b];
        int mnew, inew;
        if (t == 0) { mnew = 1; inew = idx; }
        else {
            int mp = g_ms[b];
            inew = idx * mp;
            int prev = g_si[b] * mp;
            mnew = (inew != prev) ? 1 : 0;
        }
        float S = nll;
        #pragma unroll
        for (int s = 16; s; s >>= 1) S += __shfl_xor_sync(0xffffffffu, S, s);
        S *= (1.f / 32.f);
        int cnt = mnew;
        #pragma unroll
        for (int s = 16; s; s >>= 1) cnt += __shfl_xor_sync(0xffffffffu, cnt, s);
        if (b == 0) g_loss += S * (float)cnt * (1.f / (32.f * 4.f));
        g_si[b] = inew; g_ms[b] = mnew;
        g_res_s[t][b] = inew; g_res_ms[t][b] = mnew;
        sidx[b] = inew;
    }
    __syncthreads();
    for (int x = tid; x < 32*512; x += 256) {
        int b = x >> 9, k = x & 511;
        g_ucat[b*1024 + k] = U[((size_t)b*Mz + sidx[b])*512 + k];
    }
}

// ------------------------- control: e-phase ---------------------------------
__global__ void ctrl_e_kernel(int t)
{
    int b = threadIdx.x;
    if (b < 32) {
        float nll = g_nll[b];
        int idx = g_amax_i[b];
        int mnew, inew;
        if (t == 0) { mnew = 1; inew = idx; }
        else {
            int mp = g_me[b];
            inew = idx * mp;
            int prev = g_ei[b] * mp;
            mnew = (inew != prev) ? 1 : 0;
        }
        float S = nll;
        #pragma unroll
        for (int s = 16; s; s >>= 1) S += __shfl_xor_sync(0xffffffffu, S, s);
        S *= (1.f / 32.f);
        int cnt = mnew;
        #pragma unroll
        for (int s = 16; s; s >>= 1) cnt += __shfl_xor_sync(0xffffffffu, cnt, s);
        if (b == 0) g_loss += S * (float)cnt * (1.f / (32.f * 4.f));
        g_ei[b] = inew; g_me[b] = mnew;
        g_res_e[t][b] = inew; g_res_me[t][b] = mnew;
    }
}

// ------------------------- final output -------------------------------------
__global__ void final_kernel(float* __restrict__ out, int out_size)
{
    int tid = threadIdx.x;
    if (tid < 32) {
        int b = tid;
        int ps = 0, pe = 0;
        #pragma unroll
        for (int t = 0; t < 4; t++) { ps += g_res_ms[t][b]; pe += g_res_me[t][b]; }
        int p1 = g_res_s[ps - 1][b];
        int p2 = g_res_e[pe - 1][b];
        if (1  + b < out_size) out[1  + b] = (float)p1;
        if (33 + b < out_size) out[33 + b] = (float)p2;
        if (b == 0 && out_size > 0) out[0] = g_loss;
    }
}

// ------------------------- launch -------------------------------------------
extern "C" void kernel_launch(void* const* d_in, const int* in_sizes, int n_in,
                              void* d_out, int out_size)
{
    const float* U      = (const float*)d_in[0];
    const int*   dmask  = (const int*)  d_in[1];
    const int*   span   = (const int*)  d_in[2];
    const float* Wih    = (const float*)d_in[3];
    const float* Whh    = (const float*)d_in[4];
    const float* bih    = (const float*)d_in[5];
    const float* bhh    = (const float*)d_in[6];
    const float* WsLin  = (const float*)d_in[7];
    const float* WsM1   = (const float*)d_in[8];
    const float* bsM1   = (const float*)d_in[9];
    const float* WsM2   = (const float*)d_in[10];
    const float* bsM2   = (const float*)d_in[11];
    const float* WsM12  = (const float*)d_in[12];
    const float* bsM12  = (const float*)d_in[13];
    const float* WeLin  = (const float*)d_in[14];
    const float* WeM1   = (const float*)d_in[15];
    const float* beM1   = (const float*)d_in[16];
    const float* WeM2   = (const float*)d_in[17];
    const float* beM2   = (const float*)d_in[18];
    const float* WeM12  = (const float*)d_in[19];
    const float* beM12  = (const float*)d_in[20];
    (void)in_sizes; (void)n_in;

    cudaFuncSetAttribute(gemm_mma<0>, cudaFuncAttributeMaxDynamicSharedMemorySize, GSMEM_TOTAL);
    cudaFuncSetAttribute(gemm_mma<1>, cudaFuncAttributeMaxDynamicSharedMemorySize, GSMEM_TOTAL);

    float *preAddr=nullptr, *m2Addr=nullptr;
    bf16 *Uh=nullptr,*Ul=nullptr,*W1sh=nullptr,*W1sl=nullptr,*W1eh=nullptr,*W1el=nullptr;
    bf16 *W2sh=nullptr,*W2sl=nullptr,*W2eh=nullptr,*W2el=nullptr,*m1h=nullptr,*m1l=nullptr;
    cudaGetSymbolAddress((void**)&preAddr, g_pre);
    cudaGetSymbolAddress((void**)&m2Addr,  g_m2max);
    cudaGetSymbolAddress((void**)&Uh,   g_Uh);   cudaGetSymbolAddress((void**)&Ul,   g_Ul);
    cudaGetSymbolAddress((void**)&W1sh, g_W1sh); cudaGetSymbolAddress((void**)&W1sl, g_W1sl);
    cudaGetSymbolAddress((void**)&W1eh, g_W1eh); cudaGetSymbolAddress((void**)&W1el, g_W1el);
    cudaGetSymbolAddress((void**)&W2sh, g_W2sh); cudaGetSymbolAddress((void**)&W2sl, g_W2sl);
    cudaGetSymbolAddress((void**)&W2eh, g_W2eh); cudaGetSymbolAddress((void**)&W2el, g_W2el);
    cudaGetSymbolAddress((void**)&m1h,  g_m1h);  cudaGetSymbolAddress((void**)&m1l,  g_m1l);

    // launch 0
    init_kernel<<<Bz, 256>>>(dmask);

    // launch 1: fused bf16 hi/lo splits (5 segments)
    {
        CvtSeg s0 = { U,     Uh,   Ul,   (long long)NR  * KPRE, KPRE, KPRE };
        CvtSeg s1 = { WsM1,  W1sh, W1sl, (long long)HPz * KPRE, 768,  KPRE };
        CvtSeg s2 = { WeM1,  W1eh, W1el, (long long)HPz * KPRE, 768,  KPRE };
        CvtSeg s3 = { WsM2,  W2sh, W2sl, (long long)HPz * KM2,  KM2,  KM2 };
        CvtSeg s4 = { WeM2,  W2eh, W2el, (long long)HPz * KM2,  KM2,  KM2 };
        long long total = s0.total + s1.total + s2.total + s3.total + s4.total;
        unsigned grid = (unsigned)((total + 255) / 256);
        cvt_fused_kernel<<<grid, 256>>>(s0, s1, s2, s3, s4);
    }

    // launches 2-4: t=0 LSTM trio (independent of the GEMMs)
    gather_kernel<<<Bz, 256>>>(U);
    gates_kernel<<<dim3(8, Bz), 128>>>(Wih, Whh, bih, bhh);
    act_kernel<<<Bz, 256>>>();

    // launch 5 (ncu -s 5 -c 1 profiles this): preU GEMM, start head
    gemm_mma<0><<<dim3(32, 150), 256, GSMEM_TOTAL>>>(Uh, Ul, W1sh, W1sl, nullptr,
                                                     preAddr, KPRE);
    gemm_mma<0><<<dim3(32, 150), 256, GSMEM_TOTAL>>>(Uh, Ul, W1eh, W1el, nullptr,
                                                     preAddr + (size_t)NR*HPz, KPRE);

    for (int t = 0; t < 4; t++) {
        if (t > 0) {
            gather_kernel<<<Bz, 256>>>(U);
            gates_kernel<<<dim3(8, Bz), 128>>>(Wih, Whh, bih, bhh);
            act_kernel<<<Bz, 256>>>();
        }

        // ---- start head ----
        r_kernel<<<dim3(2, Bz), 128>>>(WsLin);
        rw_kernel<<<dim3(16, Bz), 256>>>(WsM1, bsM1);
        m1max_kernel<<<NR, 256>>>(0);
        gemm_mma<1><<<dim3(32, 150), 256, GSMEM_TOTAL>>>(m1h, m1l, W2sh, W2sl, bsM2,
                                                         m2Addr, KM2);
        alpha_kernel<<<NR/8, 256>>>(WsM12, bsM12, dmask);
        reduce_kernel<<<Bz, 256>>>(span, 0);
        ctrl_s_kernel<<<1, 256>>>(U, t);

        // ---- end head ----
        r_kernel<<<dim3(2, Bz), 128>>>(WeLin);
        rw_kernel<<<dim3(16, Bz), 256>>>(WeM1, beM1);
        m1max_kernel<<<NR, 256>>>(1);
        gemm_mma<1><<<dim3(32, 150), 256, GSMEM_TOTAL>>>(m1h, m1l, W2eh, W2el, beM2,
                                                         m2Addr, KM2);
        alpha_kernel<<<NR/8, 256>>>(WeM12, beM12, dmask);
        reduce_kernel<<<Bz, 256>>>(span, 1);
        ctrl_e_kernel<<<1, 32>>>(t);
    }

    final_kernel<<<1, 32>>>((float*)d_out, out_size);
}

// round 16
// speedup vs baseline: 1.0796x; 1.0796x over previous
#include <cuda_runtime.h>
#include <cuda_bf16.h>
#include <cstdint>
#include <cstddef>

// ---------------------------------------------------------------------------
// DynamicDecoder: H=256, P=16, T=4, B=32, M=600
//   preU[head][n][4096] = U[n,:512] @ W1[:, :512]^T   -- mma.sync bf16 3-term
//   per step/head: rw = r@W1_r^T + b1 (tiny); m1 = max_p(preU + rw)
//                  m2max = 16-group max of (m1 @ W2^T + b2)  -- mma.sync bf16
//                  alpha = max_j16(cat[m1,m2max].W12^T + b12) + mask
//                  log-softmax reduce -> argmax / nll
// fp32 operands split into bf16 hi/lo; 3-term MMA (hh,hl,lh) in fp32 accum.
// GEMV kernels (gates, r) use warp-per-row + shfl reduce (occupancy fix).
// Launch order puts gemm_mma<0> at my index 3 = overall launch #5 so the
// fixed ncu window (-s 5 -c 1, which includes 2 harness pre-launches)
// profiles the big GEMM.
// ---------------------------------------------------------------------------

#define Bz 32
#define Mz 600
#define Hz 256
#define NR (Bz*Mz)      // 19200
#define HPz 4096
#define KPRE 512
#define KM2 256

typedef unsigned long long u64;
typedef __nv_bfloat16 bf16;

// ------------------------- device scratch (no allocs) ----------------------
__device__ __align__(16) float g_pre[2ull*NR*HPz];        // 629 MB
__device__ __align__(16) float g_m1[(size_t)NR*Hz];
__device__ __align__(16) bf16  g_m1h[(size_t)NR*Hz];
__device__ __align__(16) bf16  g_m1l[(size_t)NR*Hz];
__device__ __align__(16) float g_m2max[(size_t)NR*Hz];
__device__ __align__(16) float g_alpha[NR];
__device__ __align__(16) float g_rw[Bz*HPz];
__device__ __align__(16) float g_ucat[Bz*1024];
__device__ __align__(16) float g_gates[Bz*1024];
__device__ __align__(16) float g_h[Bz*Hz];
__device__ __align__(16) float g_c[Bz*Hz];
__device__ __align__(16) float g_r[Bz*Hz];
__device__ __align__(16) bf16  g_Uh[(size_t)NR*KPRE], g_Ul[(size_t)NR*KPRE];
__device__ __align__(16) bf16  g_W1sh[(size_t)HPz*KPRE], g_W1sl[(size_t)HPz*KPRE];
__device__ __align__(16) bf16  g_W1eh[(size_t)HPz*KPRE], g_W1el[(size_t)HPz*KPRE];
__device__ __align__(16) bf16  g_W2sh[(size_t)HPz*KM2],  g_W2sl[(size_t)HPz*KM2];
__device__ __align__(16) bf16  g_W2eh[(size_t)HPz*KM2],  g_W2el[(size_t)HPz*KM2];
__device__ float g_nll[Bz];
__device__ int   g_amax_i[Bz];
__device__ int   g_si[Bz], g_ei[Bz], g_ms[Bz], g_me[Bz];
__device__ int   g_res_s[4][Bz], g_res_e[4][Bz];
__device__ int   g_res_ms[4][Bz], g_res_me[4][Bz];
__device__ float g_loss;

// ------------------------- helpers -----------------------------------------
__device__ __forceinline__ float sigm(float x) { return 1.f / (1.f + expf(-x)); }

__device__ __forceinline__ uint32_t s2u(const void* p) {
    uint32_t a;
    asm("{ .reg .u64 t; cvta.to.shared.u64 t, %1; cvt.u32.u64 %0, t; }"
        : "=r"(a) : "l"(p));
    return a;
}
#define SWZ(x) ((x) ^ (((x) >> 3) & 0x70))

__device__ __forceinline__ void cpasync16(uint32_t dst, const void* src) {
    asm volatile("cp.async.cg.shared.global [%0], [%1], 16;" :: "r"(dst), "l"(src));
}
#define CP_COMMIT() asm volatile("cp.async.commit_group;" ::: "memory")
#define CP_WAIT(n)  asm volatile("cp.async.wait_group %0;" :: "n"(n) : "memory")

__device__ __forceinline__ void ldmx4(uint32_t* r, uint32_t addr) {
    asm volatile("ldmatrix.sync.aligned.m8n8.x4.shared.b16 {%0,%1,%2,%3}, [%4];"
        : "=r"(r[0]), "=r"(r[1]), "=r"(r[2]), "=r"(r[3]) : "r"(addr));
}
__device__ __forceinline__ void mma_bf16(float* c, const uint32_t* a, const uint32_t* b) {
    asm volatile(
        "mma.sync.aligned.m16n8k16.row.col.f32.bf16.bf16.f32 "
        "{%0,%1,%2,%3}, {%4,%5,%6,%7}, {%8,%9}, {%0,%1,%2,%3};"
        : "+f"(c[0]), "+f"(c[1]), "+f"(c[2]), "+f"(c[3])
        : "r"(a[0]), "r"(a[1]), "r"(a[2]), "r"(a[3]), "r"(b[0]), "r"(b[1]));
}

// ------------------------- init ---------------------------------------------
__global__ void init_kernel(const int* __restrict__ dmask)
{
    __shared__ int ss[256];
    int b = blockIdx.x, tid = threadIdx.x;
    int s = 0;
    for (int m = tid; m < Mz; m += 256) s += dmask[b*Mz + m];
    ss[tid] = s; __syncthreads();
    for (int st = 128; st; st >>= 1) { if (tid < st) ss[tid] += ss[tid+st]; __syncthreads(); }
    if (tid == 0) { g_ei[b] = ss[0] - 1; g_si[b] = 0; if (b == 0) g_loss = 0.f; }
    g_h[b*Hz + tid] = 0.f;
    g_c[b*Hz + tid] = 0.f;
}

// ------------------------- fused fp32 -> bf16 hi/lo split (5 segments) ------
struct CvtSeg {
    const float* src; bf16* hi; bf16* lo;
    long long total; int srcStride; int C;
};
__global__ void cvt_fused_kernel(CvtSeg s0, CvtSeg s1, CvtSeg s2, CvtSeg s3, CvtSeg s4)
{
    long long i = (long long)blockIdx.x * blockDim.x + threadIdx.x;
    CvtSeg s;
    if (i < s0.total) s = s0;
    else { i -= s0.total;
        if (i < s1.total) s = s1;
        else { i -= s1.total;
            if (i < s2.total) s = s2;
            else { i -= s2.total;
                if (i < s3.total) s = s3;
                else { i -= s3.total;
                    if (i < s4.total) s = s4;
                    else return; } } } }
    long long r = i / s.C;
    int c = (int)(i - r * (long long)s.C);
    float x = s.src[r * (long long)s.srcStride + c];
    bf16 h = __float2bfloat16(x);
    s.hi[i] = h;
    s.lo[i] = __float2bfloat16(x - __bfloat162float(h));
}

// ------------------------- LSTM: gather / gates / activation ----------------
__global__ void gather_kernel(const float* __restrict__ U)
{
    int b = blockIdx.x, tid = threadIdx.x;
    int si = g_si[b], ei = g_ei[b];
    const float* us = U + ((size_t)b*Mz + si)*512;
    const float* ue = U + ((size_t)b*Mz + ei)*512;
    for (int k = tid; k < 512; k += 256) {
        g_ucat[b*1024 + k]       = us[k];
        g_ucat[b*1024 + 512 + k] = ue[k];
    }
}

// warp-per-row GEMV: 8 warps/block, row = blockIdx.x*8 + warp (0..1023), b = blockIdx.y
__global__ void gates_kernel(const float* __restrict__ Wih,
                             const float* __restrict__ Whh,
                             const float* __restrict__ bih,
                             const float* __restrict__ bhh)
{
    __shared__ __align__(16) float sx[1280];
    int b = blockIdx.y, tid = threadIdx.x;
    int w = tid >> 5, l = tid & 31;
    int row = blockIdx.x*8 + w;
    for (int k = tid; k < 1024; k += 256) sx[k]      = g_ucat[b*1024 + k];
    if (tid < 256)                        sx[1024+tid] = g_h[b*Hz + tid];
    __syncthreads();
    const float4* x4 = (const float4*)sx;       // 256 f4 (ucat)
    const float4* h4 = x4 + 256;                // 64 f4 (h)
    const float4* w1 = (const float4*)(Wih + (size_t)row*1024);
    const float4* w2 = (const float4*)(Whh + (size_t)row*256);
    float acc = 0.f;
    #pragma unroll
    for (int i = 0; i < 8; i++) {
        float4 wv = w1[l + 32*i], xv = x4[l + 32*i];
        acc += wv.x*xv.x + wv.y*xv.y + wv.z*xv.z + wv.w*xv.w;
    }
    #pragma unroll
    for (int i = 0; i < 2; i++) {
        float4 wv = w2[l + 32*i], hv = h4[l + 32*i];
        acc += wv.x*hv.x + wv.y*hv.y + wv.z*hv.z + wv.w*hv.w;
    }
    #pragma unroll
    for (int s = 16; s; s >>= 1) acc += __shfl_down_sync(0xffffffffu, acc, s);
    if (l == 0) g_gates[b*1024 + row] = acc + bih[row] + bhh[row];
}

__global__ void act_kernel()
{
    int b = blockIdx.x, i = threadIdx.x;
    float gi = g_gates[b*1024 + i], gf = g_gates[b*1024 + 256 + i];
    float gg = g_gates[b*1024 + 512 + i], go = g_gates[b*1024 + 768 + i];
    float c = sigm(gf)*g_c[b*Hz+i] + sigm(gi)*tanhf(gg);
    g_c[b*Hz+i] = c;
    g_h[b*Hz+i] = sigm(go)*tanhf(c);
}

// ------------------------- r = tanh(cat[h,ucat] @ Wlin^T), warp-per-row -----
__global__ void r_kernel(const float* __restrict__ Wlin)
{
    __shared__ __align__(16) float sx[1280];
    int b = blockIdx.y, tid = threadIdx.x;
    int w = tid >> 5, l = tid & 31;
    int row = blockIdx.x*8 + w;                 // 0..255
    if (tid < 256)                        sx[tid]     = g_h[b*Hz + tid];
    for (int k = tid; k < 1024; k += 256) sx[256 + k] = g_ucat[b*1024 + k];
    __syncthreads();
    const float4* x4 = (const float4*)sx;       // 320 f4
    const float4* wr = (const float4*)(Wlin + (size_t)row*1280);
    float acc = 0.f;
    #pragma unroll
    for (int i = 0; i < 10; i++) {
        float4 wv = wr[l + 32*i], xv = x4[l + 32*i];
        acc += wv.x*xv.x + wv.y*xv.y + wv.z*xv.z + wv.w*xv.w;
    }
    #pragma unroll
    for (int s = 16; s; s >>= 1) acc += __shfl_down_sync(0xffffffffu, acc, s);
    if (l == 0) g_r[b*Hz + row] = tanhf(acc);
}

// ------------------------- rw = r @ W1_r^T + b1 -----------------------------
__global__ void rw_kernel(const float* __restrict__ W1, const float* __restrict__ b1)
{
    __shared__ __align__(16) float sr[256];
    int b = blockIdx.y, tid = threadIdx.x;
    int j = blockIdx.x*256 + tid;
    sr[tid] = g_r[b*Hz + tid];
    __syncthreads();
    const float4* w  = (const float4*)(W1 + (size_t)j*768 + 512);
    const float4* r4 = (const float4*)sr;
    float acc = b1[j];
    #pragma unroll 8
    for (int k = 0; k < 64; k++) {
        float4 wv = w[k], rv = r4[k];
        acc += wv.x*rv.x + wv.y*rv.y + wv.z*rv.z + wv.w*rv.w;
    }
    g_rw[b*HPz + j] = acc;
}

// ------------------------- m1 = max_p(preU + rw); also split to bf16 --------
__global__ void m1max_kernel(int head)
{
    int n = blockIdx.x, h = threadIdx.x;
    int b = n / Mz;
    const float4* p = (const float4*)(g_pre + (size_t)head*((size_t)NR*HPz) + (size_t)n*HPz + h*16);
    const float4* r = (const float4*)(g_rw + b*HPz + h*16);
    float m = -1e38f;
    #pragma unroll
    for (int q = 0; q < 4; q++) {
        float4 a = p[q], c = r[q];
        m = fmaxf(m, fmaxf(fmaxf(a.x+c.x, a.y+c.y), fmaxf(a.z+c.z, a.w+c.w)));
    }
    g_m1[(size_t)n*Hz + h] = m;
    bf16 hh = __float2bfloat16(m);
    g_m1h[(size_t)n*Hz + h] = hh;
    g_m1l[(size_t)n*Hz + h] = __float2bfloat16(m - __bfloat162float(hh));
}

// ------------------------- mma.sync bf16 3-term GEMM (3-stage pipeline) -----
// C[128x128] per CTA. A rows Mbase.. (lda=K), B rows j0.. (ldb=K), NT form.
// 8 warps as 4(m) x 2(n); warp tile 32x64 via m16n8k16.
// EPI=0: store fp32 C to out (ldc=4096). EPI=1: +bias, 16-group max (ldc=256).
// smem: [0,512) bias; [1024, 1024+3*65536) three stages of {Ah,Al,Bh,Bl}.
#define GSMEM_TOTAL (1024 + 3*65536)

template<int EPI>
__global__ __launch_bounds__(256)
void gemm_mma(const bf16* __restrict__ Ah, const bf16* __restrict__ Al,
              const bf16* __restrict__ Bh, const bf16* __restrict__ Bl,
              const float* __restrict__ bias,
              float* __restrict__ out, int K)
{
    extern __shared__ __align__(1024) char smem[];
    uint32_t sb = s2u(smem);
    const int tid = threadIdx.x, wid = tid >> 5, lane = tid & 31;
    const int Mbase = blockIdx.y * 128, j0 = blockIdx.x * 128;

    if (EPI == 1 && tid < 128) ((float*)smem)[tid] = bias[j0 + tid];

    float acc[2][8][4];
    #pragma unroll
    for (int a = 0; a < 2; a++)
        #pragma unroll
        for (int b = 0; b < 8; b++)
            #pragma unroll
            for (int d = 0; d < 4; d++) acc[a][b][d] = 0.f;

    const int wm = (wid & 3) * 32, wn = (wid >> 2) * 64;
    // ldmatrix per-lane source coordinates
    const int arow = wm + (lane & 15);
    const int acol = (lane >> 4) << 4;                 // 0 or 16 bytes (k half)
    const int brow = wn + (lane & 7) + ((lane >> 4) << 3);
    const int bcol = ((lane >> 3) & 1) << 4;

    const int KB = K >> 6;

    auto load_stage = [&](int kb, int buf) {
        const int kofs = kb * 64;
        #pragma unroll
        for (int q = 0; q < 4; q++) {
            int i = q * 256 + tid;
            int r = i >> 3, c = i & 7;
            uint32_t dst = sb + 1024 + buf * 65536 + SWZ((uint32_t)(r * 128 + c * 16));
            size_t ga = (size_t)(Mbase + r) * K + kofs + c * 8;
            size_t gb = (size_t)(j0   + r) * K + kofs + c * 8;
            cpasync16(dst,         Ah + ga);
            cpasync16(dst + 16384, Al + ga);
            cpasync16(dst + 32768, Bh + gb);
            cpasync16(dst + 49152, Bl + gb);
        }
    };

    load_stage(0, 0); CP_COMMIT();
    if (KB > 1) { load_stage(1, 1); CP_COMMIT(); }

    for (int kb = 0; kb < KB; kb++) {
        if (kb + 1 < KB) { CP_WAIT(1); } else { CP_WAIT(0); }
        __syncthreads();
        int buf = kb % 3;
        uint32_t ab = sb + 1024 + buf * 65536;
        #pragma unroll
        for (int ks = 0; ks < 4; ks++) {
            uint32_t a_h[2][4], a_l[2][4], b_h[4][4], b_l[4][4];
            #pragma unroll
            for (int mt = 0; mt < 2; mt++) {
                uint32_t sw = SWZ((uint32_t)((arow + mt*16) * 128 + ks*32 + acol));
                ldmx4(a_h[mt], ab + sw);
                ldmx4(a_l[mt], ab + 16384 + sw);
            }
            #pragma unroll
            for (int np = 0; np < 4; np++) {
                uint32_t sw = SWZ((uint32_t)((brow + np*16) * 128 + ks*32 + bcol));
                ldmx4(b_h[np], ab + 32768 + sw);
                ldmx4(b_l[np], ab + 49152 + sw);
            }
            #pragma unroll
            for (int mt = 0; mt < 2; mt++)
                #pragma unroll
                for (int nt = 0; nt < 8; nt++) {
                    const uint32_t* bh2 = &b_h[nt >> 1][(nt & 1) * 2];
                    const uint32_t* bl2 = &b_l[nt >> 1][(nt & 1) * 2];
                    mma_bf16(acc[mt][nt], a_h[mt], bh2);
                    mma_bf16(acc[mt][nt], a_h[mt], bl2);
                    mma_bf16(acc[mt][nt], a_l[mt], bh2);
                }
        }
        __syncthreads();
        if (kb + 2 < KB) { load_stage(kb + 2, (kb + 2) % 3); CP_COMMIT(); }
    }

    if (EPI == 0) {
        #pragma unroll
        for (int mt = 0; mt < 2; mt++)
            #pragma unroll
            for (int nt = 0; nt < 8; nt++) {
                int row = Mbase + wm + mt*16 + (lane >> 2);
                int col = j0 + wn + nt*8 + 2*(lane & 3);
                *(float2*)(out + (size_t)row       * HPz + col) =
                    make_float2(acc[mt][nt][0], acc[mt][nt][1]);
                *(float2*)(out + (size_t)(row + 8) * HPz + col) =
                    make_float2(acc[mt][nt][2], acc[mt][nt][3]);
            }
    } else {
        float* Cs = (float*)(smem + 1024);   // reuse stage 0: 128x128 f32 = 64KB
        #pragma unroll
        for (int mt = 0; mt < 2; mt++)
            #pragma unroll
            for (int nt = 0; nt < 8; nt++) {
                int r0 = wm + mt*16 + (lane >> 2);
                int c0 = wn + nt*8 + 2*(lane & 3);
                Cs[r0*128 + c0]       = acc[mt][nt][0];
                Cs[r0*128 + c0 + 1]   = acc[mt][nt][1];
                Cs[(r0+8)*128 + c0]   = acc[mt][nt][2];
                Cs[(r0+8)*128 + c0+1] = acc[mt][nt][3];
            }
        __syncthreads();
        const float* sbias = (const float*)smem;
        for (int i = tid; i < 1024; i += 256) {
            int r = i >> 3, g = i & 7;
            const float* row = Cs + r*128 + g*16;
            const float* bb  = sbias + g*16;
            float m = -1e38f;
            #pragma unroll
            for (int k = 0; k < 16; k++) m = fmaxf(m, row[k] + bb[k]);
            out[(size_t)(Mbase + r) * Hz + blockIdx.x*8 + g] = m;
        }
    }
}

// ------------------------- alpha = max_j16(cat[m1,m2max].W12[j]+b12)+mask ---
__global__ void alpha_kernel(const float* __restrict__ W12,
                             const float* __restrict__ b12,
                             const int*   __restrict__ dmask)
{
    __shared__ __align__(16) float sw[16 * 512];
    __shared__ float sb[16];
    int tid = threadIdx.x;
    for (int i = tid; i < 8192; i += 256) sw[i] = W12[i];
    if (tid < 16) sb[tid] = b12[tid];
    __syncthreads();
    int w = tid >> 5, lane = tid & 31;
    int n = blockIdx.x * 8 + w;
    const float4* m1p = (const float4*)(g_m1    + (size_t)n*Hz);
    const float4* m2p = (const float4*)(g_m2max + (size_t)n*Hz);
    float4 a0 = m1p[lane], a1 = m1p[32 + lane];
    float4 c0 = m2p[lane], c1 = m2p[32 + lane];
    float vmax = -1e38f;
    #pragma unroll
    for (int j = 0; j < 16; j++) {
        const float4* wr = (const float4*)(sw + j*512);
        float4 w0 = wr[lane],      w1 = wr[32 + lane];
        float4 w2 = wr[64 + lane], w3 = wr[96 + lane];
        float p = a0.x*w0.x + a0.y*w0.y + a0.z*w0.z + a0.w*w0.w
                + a1.x*w1.x + a1.y*w1.y + a1.z*w1.z + a1.w*w1.w
                + c0.x*w2.x + c0.y*w2.y + c0.z*w2.z + c0.w*w2.w
                + c1.x*w3.x + c1.y*w3.y + c1.z*w3.z + c1.w*w3.w;
        #pragma unroll
        for (int s = 16; s; s >>= 1) p += __shfl_down_sync(0xffffffffu, p, s);
        if (lane == 0) vmax = fmaxf(vmax, p + sb[j]);
    }
    if (lane == 0) {
        int b = n / Mz, m = n - b*Mz;
        float mm = dmask[b*Mz + m] ? 0.f : -1e30f;
        g_alpha[n] = vmax + mm;
    }
}

// ------------------------- per-batch argmax + log-softmax reduce ------------
__global__ void reduce_kernel(const int* __restrict__ span, int col)
{
    __shared__ float sv[256];
    __shared__ int   sidx[256];
    int b = blockIdx.x, tid = threadIdx.x;
    const float* a = g_alpha + b*Mz;
    float lv = -1e38f; int li = 0;
    for (int m = tid; m < Mz; m += 256) { float v = a[m]; if (v > lv) { lv = v; li = m; } }
    sv[tid] = lv; sidx[tid] = li; __syncthreads();
    for (int s = 128; s; s >>= 1) {
        if (tid < s) {
            float v = sv[tid+s]; int i2 = sidx[tid+s];
            if (v > sv[tid] || (v == sv[tid] && i2 < sidx[tid])) { sv[tid] = v; sidx[tid] = i2; }
        }
        __syncthreads();
    }
    float amax = sv[0]; int ai = sidx[0];
    __syncthreads();
    float se = 0.f;
    for (int m = tid; m < Mz; m += 256) se += expf(a[m] - amax);
    sv[tid] = se; __syncthreads();
    for (int s = 128; s; s >>= 1) { if (tid < s) sv[tid] += sv[tid+s]; __syncthreads(); }
    if (tid == 0) {
        float logZ = amax + logf(sv[0]);
        int tgt = span[b*2 + col];
        g_nll[b]    = -(a[tgt] - logZ);
        g_amax_i[b] = ai;
    }
}

// ------------------------- control: s-phase (also regathers u_s) ------------
__global__ void ctrl_s_kernel(const float* __restrict__ U, int t)
{
    __shared__ int sidx[32];
    int tid = threadIdx.x;
    if (tid < 32) {
        int b = tid;
        float nll = g_nll[b];
        int idx = g_amax_i[b];
        int mnew, inew;
        if (t == 0) { mnew = 1; inew = idx; }
        else {
            int mp = g_ms[b];
            inew = idx * mp;
            int prev = g_si[b] * mp;
            mnew = (inew != prev) ? 1 : 0;
        }
        float S = nll;
        #pragma unroll
        for (int s = 16; s; s >>= 1) S += __shfl_xor_sync(0xffffffffu, S, s);
        S *= (1.f / 32.f);
        int cnt = mnew;
        #pragma unroll
        for (int s = 16; s; s >>= 1) cnt += __shfl_xor_sync(0xffffffffu, cnt, s);
        if (b == 0) g_loss += S * (float)cnt * (1.f / (32.f * 4.f));
        g_si[b] = inew; g_ms[b] = mnew;
        g_res_s[t][b] = inew; g_res_ms[t][b] = mnew;
        sidx[b] = inew;
    }
    __syncthreads();
    for (int x = tid; x < 32*512; x += 256) {
        int b = x >> 9, k = x & 511;
        g_ucat[b*1024 + k] = U[((size_t)b*Mz + sidx[b])*512 + k];
    }
}

// ------------------------- control: e-phase ---------------------------------
__global__ void ctrl_e_kernel(int t)
{
    int b = threadIdx.x;
    if (b < 32) {
        float nll = g_nll[b];
        int idx = g_amax_i[b];
        int mnew, inew;
        if (t == 0) { mnew = 1; inew = idx; }
        else {
            int mp = g_me[b];
            inew = idx * mp;
            int prev = g_ei[b] * mp;
            mnew = (inew != prev) ? 1 : 0;
        }
        float S = nll;
        #pragma unroll
        for (int s = 16; s; s >>= 1) S += __shfl_xor_sync(0xffffffffu, S, s);
        S *= (1.f / 32.f);
        int cnt = mnew;
        #pragma unroll
        for (int s = 16; s; s >>= 1) cnt += __shfl_xor_sync(0xffffffffu, cnt, s);
        if (b == 0) g_loss += S * (float)cnt * (1.f / (32.f * 4.f));
        g_ei[b] = inew; g_me[b] = mnew;
        g_res_e[t][b] = inew; g_res_me[t][b] = mnew;
    }
}

// ------------------------- final output -------------------------------------
__global__ void final_kernel(float* __restrict__ out, int out_size)
{
    int tid = threadIdx.x;
    if (tid < 32) {
        int b = tid;
        int ps = 0, pe = 0;
        #pragma unroll
        for (int t = 0; t < 4; t++) { ps += g_res_ms[t][b]; pe += g_res_me[t][b]; }
        int p1 = g_res_s[ps - 1][b];
        int p2 = g_res_e[pe - 1][b];
        if (1  + b < out_size) out[1  + b] = (float)p1;
        if (33 + b < out_size) out[33 + b] = (float)p2;
        if (b == 0 && out_size > 0) out[0] = g_loss;
    }
}

// ------------------------- launch -------------------------------------------
extern "C" void kernel_launch(void* const* d_in, const int* in_sizes, int n_in,
                              void* d_out, int out_size)
{
    const float* U      = (const float*)d_in[0];
    const int*   dmask  = (const int*)  d_in[1];
    const int*   span   = (const int*)  d_in[2];
    const float* Wih    = (const float*)d_in[3];
    const float* Whh    = (const float*)d_in[4];
    const float* bih    = (const float*)d_in[5];
    const float* bhh    = (const float*)d_in[6];
    const float* WsLin  = (const float*)d_in[7];
    const float* WsM1   = (const float*)d_in[8];
    const float* bsM1   = (const float*)d_in[9];
    const float* WsM2   = (const float*)d_in[10];
    const float* bsM2   = (const float*)d_in[11];
    const float* WsM12  = (const float*)d_in[12];
    const float* bsM12  = (const float*)d_in[13];
    const float* WeLin  = (const float*)d_in[14];
    const float* WeM1   = (const float*)d_in[15];
    const float* beM1   = (const float*)d_in[16];
    const float* WeM2   = (const float*)d_in[17];
    const float* beM2   = (const float*)d_in[18];
    const float* WeM12  = (const float*)d_in[19];
    const float* beM12  = (const float*)d_in[20];
    (void)in_sizes; (void)n_in;

    cudaFuncSetAttribute(gemm_mma<0>, cudaFuncAttributeMaxDynamicSharedMemorySize, GSMEM_TOTAL);
    cudaFuncSetAttribute(gemm_mma<1>, cudaFuncAttributeMaxDynamicSharedMemorySize, GSMEM_TOTAL);

    float *preAddr=nullptr, *m2Addr=nullptr;
    bf16 *Uh=nullptr,*Ul=nullptr,*W1sh=nullptr,*W1sl=nullptr,*W1eh=nullptr,*W1el=nullptr;
    bf16 *W2sh=nullptr,*W2sl=nullptr,*W2eh=nullptr,*W2el=nullptr,*m1h=nullptr,*m1l=nullptr;
    cudaGetSymbolAddress((void**)&preAddr, g_pre);
    cudaGetSymbolAddress((void**)&m2Addr,  g_m2max);
    cudaGetSymbolAddress((void**)&Uh,   g_Uh);   cudaGetSymbolAddress((void**)&Ul,   g_Ul);
    cudaGetSymbolAddress((void**)&W1sh, g_W1sh); cudaGetSymbolAddress((void**)&W1sl, g_W1sl);
    cudaGetSymbolAddress((void**)&W1eh, g_W1eh); cudaGetSymbolAddress((void**)&W1el, g_W1el);
    cudaGetSymbolAddress((void**)&W2sh, g_W2sh); cudaGetSymbolAddress((void**)&W2sl, g_W2sl);
    cudaGetSymbolAddress((void**)&W2eh, g_W2eh); cudaGetSymbolAddress((void**)&W2el, g_W2el);
    cudaGetSymbolAddress((void**)&m1h,  g_m1h);  cudaGetSymbolAddress((void**)&m1l,  g_m1l);

    // my launch 0 (overall #2 after 2 harness pre-launches)
    init_kernel<<<Bz, 256>>>(dmask);

    // my launch 1: fused bf16 hi/lo splits (5 segments)
    {
        CvtSeg s0 = { U,     Uh,   Ul,   (long long)NR  * KPRE, KPRE, KPRE };
        CvtSeg s1 = { WsM1,  W1sh, W1sl, (long long)HPz * KPRE, 768,  KPRE };
        CvtSeg s2 = { WeM1,  W1eh, W1el, (long long)HPz * KPRE, 768,  KPRE };
        CvtSeg s3 = { WsM2,  W2sh, W2sl, (long long)HPz * KM2,  KM2,  KM2 };
        CvtSeg s4 = { WeM2,  W2eh, W2el, (long long)HPz * KM2,  KM2,  KM2 };
        long long total = s0.total + s1.total + s2.total + s3.total + s4.total;
        unsigned grid = (unsigned)((total + 255) / 256);
        cvt_fused_kernel<<<grid, 256>>>(s0, s1, s2, s3, s4);
    }

    // my launch 2: gather (independent of GEMMs)
    gather_kernel<<<Bz, 256>>>(U);

    // my launch 3 = overall #5: ncu -s 5 -c 1 profiles THIS preU GEMM
    gemm_mma<0><<<dim3(32, 150), 256, GSMEM_TOTAL>>>(Uh, Ul, W1sh, W1sl, nullptr,
                                                     preAddr, KPRE);
    gemm_mma<0><<<dim3(32, 150), 256, GSMEM_TOTAL>>>(Uh, Ul, W1eh, W1el, nullptr,
                                                     preAddr + (size_t)NR*HPz, KPRE);

    // t=0 LSTM gates/act after the GEMMs (no dependence)
    gates_kernel<<<dim3(128, Bz), 256>>>(Wih, Whh, bih, bhh);
    act_kernel<<<Bz, 256>>>();

    for (int t = 0; t < 4; t++) {
        if (t > 0) {
            gather_kernel<<<Bz, 256>>>(U);
            gates_kernel<<<dim3(128, Bz), 256>>>(Wih, Whh, bih, bhh);
            act_kernel<<<Bz, 256>>>();
        }

        // ---- start head ----
        r_kernel<<<dim3(32, Bz), 256>>>(WsLin);
        rw_kernel<<<dim3(16, Bz), 256>>>(WsM1, bsM1);
        m1max_kernel<<<NR, 256>>>(0);
        gemm_mma<1><<<dim3(32, 150), 256, GSMEM_TOTAL>>>(m1h, m1l, W2sh, W2sl, bsM2,
                                                         m2Addr, KM2);
        alpha_kernel<<<NR/8, 256>>>(WsM12, bsM12, dmask);
        reduce_kernel<<<Bz, 256>>>(span, 0);
        ctrl_s_kernel<<<1, 256>>>(U, t);

        // ---- end head ----
        r_kernel<<<dim3(32, Bz), 256>>>(WeLin);
        rw_kernel<<<dim3(16, Bz), 256>>>(WeM1, beM1);
        m1max_kernel<<<NR, 256>>>(1);
        gemm_mma<1><<<dim3(32, 150), 256, GSMEM_TOTAL>>>(m1h, m1l, W2eh, W2el, beM2,
                                                         m2Addr, KM2);
        alpha_kernel<<<NR/8, 256>>>(WeM12, beM12, dmask);
        reduce_kernel<<<Bz, 256>>>(span, 1);
        ctrl_e_kernel<<<1, 32>>>(t);
    }

    final_kernel<<<1, 32>>>((float*)d_out, out_size);
}